// round 14
// baseline (speedup 1.0000x reference)
#include <cuda_runtime.h>
#include <cuda_fp16.h>
#include <math.h>

#define NN 50000
#define NE 800000
#define NTILES 98      // ceil((NN+1)/512)
#define GSTRIDE 68     // A smem stride (conflict-free frag loads)
#define AGGQ 8         // edges per half-warp quota
#define GEMM_SMEM (64 * GSTRIDE * 4 + 6144 * 8)   // 17408 + 49152 = 66560 B

// ---------------- scratch (static __device__, allocation-free) ----------------
__device__ uint4  g_projh[NN * 16];     // [N][16] x 16B: {b0 4h | b1 4h} per sub
__device__ float4 g_h1a[NN * 16];       // layer-1 hidden fp32
__device__ float4 g_h2a[NN * 16];       // layer-2 hidden fp32
__device__ int    g_deg[NN];            // self-clearing (scan zeroes after read)
__device__ int    g_cursor[NN];
__device__ int    g_tflag[128];         // cleared by scatter each run
__device__ int2   g_csr[NE];            // {src | etype<<17, dst}
__device__ float  g_facc;
__device__ int    g_fcnt;
__device__ float  g_sink;

static __device__ __forceinline__ unsigned f2tf32(float f)
{
    unsigned u;
    asm("cvt.rna.tf32.f32 %0, %1;" : "=r"(u) : "f"(f));
    return u;
}

// ---------------- CSR build (side stream) ----------------
// hist also resets the FC accumulator (stream-ordered before fc via ePref).
__global__ void __launch_bounds__(256) hist_kernel(const int4* __restrict__ dst4,
                                                   int* __restrict__ deg)
{
    if (blockIdx.x == 0 && threadIdx.x == 0) { g_facc = 0.f; g_fcnt = 0; }
    int t = blockIdx.x * 256 + threadIdx.x;
    if (t >= NE / 4) return;
    int4 d = __ldg(dst4 + t);
    atomicAdd(&deg[d.x], 1);
    atomicAdd(&deg[d.y], 1);
    atomicAdd(&deg[d.z], 1);
    atomicAdd(&deg[d.w], 1);
}

// Warp-shuffle decoupled-lookback scan; self-clears deg for the next replay.
__global__ void __launch_bounds__(512) scan_kernel(
    int* __restrict__ deg, int* __restrict__ cursor, int* __restrict__ tflag)
{
    __shared__ int wsum[16];
    __shared__ int wpre[16];
    __shared__ int s_prefix;
    const int t = threadIdx.x;
    const int warp = t >> 5;
    const int lane = t & 31;
    const int tile = blockIdx.x;
    const int g = tile * 512 + t;

    int v = (g < NN) ? deg[g] : 0;
    int x = v;
#pragma unroll
    for (int d = 1; d < 32; d <<= 1) {
        int y = __shfl_up_sync(0xFFFFFFFFu, x, d);
        if (lane >= d) x += y;
    }
    if (lane == 31) wsum[warp] = x;
    if (t == 32) s_prefix = 0;
    __syncthreads();

    if (warp == 0 && lane < 16) {
        int s = wsum[lane];
        int p = s;
#pragma unroll
        for (int d = 1; d < 16; d <<= 1) {
            int y = __shfl_up_sync(0xFFFFu, p, d);
            if (lane >= d) p += y;
        }
        wpre[lane] = p - s;
        if (lane == 15) atomicExch(&tflag[tile], p + 1);
    }

    if (tile > 0 && warp == 1) {
        int sum = 0;
        for (int base = tile - 1; base >= 0; base -= 32) {
            int idx = base - lane;
            int val = 0;
            if (idx >= 0) {
                int f;
                do { f = atomicAdd(&tflag[idx], 0); } while (f == 0);
                val = f - 1;
            }
#pragma unroll
            for (int o = 16; o; o >>= 1) val += __shfl_xor_sync(0xFFFFFFFFu, val, o);
            sum += val;
        }
        if (lane == 0) s_prefix = sum;
    }
    __syncthreads();

    if (g < NN) {
        cursor[g] = s_prefix + wpre[warp] + x - v;
        deg[g] = 0;
    }
}

// 1 edge/thread; block 0 clears tflag (stream-ordered after scan).
__global__ void __launch_bounds__(256) scatter_kernel(
    const int* __restrict__ src, const int* __restrict__ dst,
    const int* __restrict__ et, int* __restrict__ cursor,
    int2* __restrict__ csr, int* __restrict__ tflag)
{
    if (blockIdx.x == 0 && threadIdx.x < 128) tflag[threadIdx.x] = 0;
    int e = blockIdx.x * 256 + threadIdx.x;
    if (e >= NE) return;
    int d = __ldg(dst + e);
    int pos = atomicAdd(&cursor[d], 1);
    csr[pos] = make_int2(__ldg(src + e) | (__ldg(et + e) << 17), d);
}

// L2 warmer for fc_w
__global__ void __launch_bounds__(256) prefetch_kernel(const float4* __restrict__ w)
{
    int tid = blockIdx.x * 256 + threadIdx.x;
    float s = 0.f;
    for (int i = tid; i < NN * 16; i += 256 * 256) {
        float4 v = __ldg(w + i);
        s += v.x + v.y + v.z + v.w;
    }
    if (s == 1.2345e37f) g_sink = s;
}

// ---------------------------------------------------------------------------
// Tensor-core node GEMM: [50000x64] @ [64x192] via mma.sync.m16n8k8.tf32.
// Weights staged per-CTA into dynamic smem (fragment-major tf32) -> LDS.64
// B-frag loads; no separate wprep kernel. Coalesced smem-staged epilogue.
// 3 CTAs/SM (80 regs, 65KB smem each; 195KB/SM <= 228KB).
// ---------------------------------------------------------------------------
__global__ void __launch_bounds__(256, 3) gemm_tc(
    const float* __restrict__ x, const float* __restrict__ V,
    const float* __restrict__ lw, const float* __restrict__ bias,
    __half* __restrict__ projh, float* __restrict__ h, int relu_in)
{
    extern __shared__ __align__(16) unsigned smem_[];
    unsigned* xs = smem_;                     // 64*GSTRIDE words (17408 B)
    uint2* wsm = (uint2*)(smem_ + 64 * GSTRIDE);   // 6144 uint2 (49152 B)

    const int tid = threadIdx.x;
    const int nbase = blockIdx.x * 64;

    // ---- stage weights: fragment-major tf32 {b0,b1} ----
    for (int i = tid; i < 6144; i += 256) {
        int nt = i >> 8;
        int s  = (i >> 5) & 7;
        int ln = i & 31;
        int o  = nt * 8 + (ln >> 2);
        int k0 = s * 8 + (ln & 3);
        float w0, w1;
        if (o < 128) {
            int b = o >> 6, c = o & 63;
            w0 = __ldg(V + ((b * 64) + k0) * 64 + c);
            w1 = __ldg(V + ((b * 64) + k0 + 4) * 64 + c);
        } else {
            w0 = __ldg(lw + k0 * 64 + (o - 128));
            w1 = __ldg(lw + (k0 + 4) * 64 + (o - 128));
        }
        wsm[i] = make_uint2(f2tf32(w0), f2tf32(w1));
    }

    // ---- stage A as tf32 ----
    {
        int nl = tid >> 2;
        int c0 = (tid & 3) * 16;
        int n = nbase + nl;
        const float4* xr = (const float4*)(x + (size_t)n * 64 + c0);
#pragma unroll
        for (int u = 0; u < 4; ++u) {
            float4 v = (n < NN) ? __ldg(xr + u) : make_float4(0.f, 0.f, 0.f, 0.f);
            if (relu_in) {
                v.x = fmaxf(v.x, 0.f); v.y = fmaxf(v.y, 0.f);
                v.z = fmaxf(v.z, 0.f); v.w = fmaxf(v.w, 0.f);
            }
            unsigned* dstp = xs + nl * GSTRIDE + c0 + u * 4;
            dstp[0] = f2tf32(v.x); dstp[1] = f2tf32(v.y);
            dstp[2] = f2tf32(v.z); dstp[3] = f2tf32(v.w);
        }
    }
    __syncthreads();

    const int w    = tid >> 5;
    const int lane = tid & 31;
    const int m0   = (w & 3) << 4;
    const int ng   = w >> 2;
    const int g    = lane >> 2;
    const int t4   = lane & 3;

    float acc[12][4];
#pragma unroll
    for (int j = 0; j < 12; ++j)
#pragma unroll
        for (int c = 0; c < 4; ++c) acc[j][c] = 0.f;

    const uint2* wp = wsm + ng * 3072 + lane;

#pragma unroll
    for (int s = 0; s < 8; ++s) {
        int k0 = s * 8;
        unsigned a0 = xs[(m0 + g) * GSTRIDE + k0 + t4];
        unsigned a1 = xs[(m0 + g + 8) * GSTRIDE + k0 + t4];
        unsigned a2 = xs[(m0 + g) * GSTRIDE + k0 + t4 + 4];
        unsigned a3 = xs[(m0 + g + 8) * GSTRIDE + k0 + t4 + 4];
        uint2 b[12];
#pragma unroll
        for (int j = 0; j < 12; ++j) b[j] = wp[(j * 8 + s) * 32];
#pragma unroll
        for (int j = 0; j < 12; ++j)
            asm volatile(
                "mma.sync.aligned.m16n8k8.row.col.f32.tf32.tf32.f32 "
                "{%0,%1,%2,%3}, {%4,%5,%6,%7}, {%8,%9}, {%0,%1,%2,%3};"
                : "+f"(acc[j][0]), "+f"(acc[j][1]), "+f"(acc[j][2]), "+f"(acc[j][3])
                : "r"(a0), "r"(a1), "r"(a2), "r"(a3), "r"(b[j].x), "r"(b[j].y));
    }
    __syncthreads();    // xs free for epilogue reuse (wsm untouched)

    // ---- Phase 1: proj (fp16, interleaved) via smem, coalesced STG.128 ----
    {
        __half* sp = (__half*)xs;             // [64][132] halves
#pragma unroll
        for (int j = 0; j < 12; ++j) {
            int o = ng * 96 + j * 8 + t4 * 2;
            if (o < 128) {
                int basis = o >> 6, c64 = o & 63;
                int off = ((c64 >> 2) << 3) + (basis << 2) + (c64 & 3);
#pragma unroll
                for (int rr = 0; rr < 2; ++rr) {
                    int nl = m0 + g + rr * 8;
                    *(__half2*)(sp + nl * 132 + off) =
                        __floats2half2_rn(acc[j][rr * 2], acc[j][rr * 2 + 1]);
                }
            }
        }
        __syncthreads();
        const unsigned* sp32 = (const unsigned*)xs;
        for (int idx = tid; idx < 1024; idx += 256) {
            int nl = idx >> 4, sub = idx & 15;
            int n = nbase + nl;
            if (n < NN) {
                int wi = nl * 66 + sub * 4;
                uint4 v = make_uint4(sp32[wi], sp32[wi + 1], sp32[wi + 2], sp32[wi + 3]);
                ((uint4*)projh)[(size_t)n * 16 + sub] = v;
            }
        }
        __syncthreads();
    }

    // ---- Phase 2: h (fp32 + bias) via smem, coalesced STG.128 ----
    {
        float* hp = (float*)xs;               // [64][66] floats
        if (ng == 1) {
#pragma unroll
            for (int j = 4; j < 12; ++j) {
                int o = 96 + j * 8 + t4 * 2;  // >= 128
                int c = o - 128;
                float b0 = __ldg(bias + c), b1 = __ldg(bias + c + 1);
#pragma unroll
                for (int rr = 0; rr < 2; ++rr) {
                    int nl = m0 + g + rr * 8;
                    float2 f;
                    f.x = acc[j][rr * 2] + b0;
                    f.y = acc[j][rr * 2 + 1] + b1;
                    *(float2*)(hp + nl * 66 + c) = f;
                }
            }
        }
        __syncthreads();
        const float* hf = (const float*)xs;
        for (int idx = tid; idx < 1024; idx += 256) {
            int nl = idx >> 4, c4 = idx & 15;
            int n = nbase + nl;
            if (n < NN) {
                int wi = nl * 66 + c4 * 4;
                float4 v = make_float4(hf[wi], hf[wi + 1], hf[wi + 2], hf[wi + 3]);
                ((float4*)h)[(size_t)n * 16 + c4] = v;
            }
        }
    }
}

// ---------------------------------------------------------------------------
// Edge-balanced aggregation: half-warp per 8-edge CSR window.
// ---------------------------------------------------------------------------
__global__ void __launch_bounds__(256) agg_kernel(
    const uint4* __restrict__ proj, const int2* __restrict__ csr,
    const float* __restrict__ comp_l, float4* __restrict__ h)
{
    __shared__ float scomp[16];
    if (threadIdx.x < 16) scomp[threadIdx.x] = comp_l[threadIdx.x];
    __syncthreads();

    int gid = blockIdx.x * 256 + threadIdx.x;
    int q = gid >> 4;
    if (q >= NE / AGGQ) return;
    int sub = gid & 15;
    int j0 = q * AGGQ;
    unsigned hmask = 0xFFFFu << (threadIdx.x & 16);

    int2 rec = (sub < AGGQ) ? __ldg(csr + j0 + sub) : make_int2(0, 0);

    int pk[AGGQ], dk[AGGQ];
#pragma unroll
    for (int k = 0; k < AGGQ; ++k) {
        pk[k] = __shfl_sync(hmask, rec.x, k, 16);
        dk[k] = __shfl_sync(hmask, rec.y, k, 16);
    }

    uint4 a[AGGQ];
#pragma unroll
    for (int k = 0; k < AGGQ; ++k)
        a[k] = __ldg(proj + (size_t)(pk[k] & 0x1FFFF) * 16 + sub);

    float4 acc = make_float4(0.f, 0.f, 0.f, 0.f);
    int cur_d = dk[0];

#define FLUSH()                                                             \
    {                                                                       \
        float4* hp = h + (size_t)cur_d * 16 + sub;                          \
        asm volatile("red.global.add.v4.f32 [%0], {%1,%2,%3,%4};"           \
                     :: "l"(hp), "f"(acc.x), "f"(acc.y), "f"(acc.z),        \
                        "f"(acc.w) : "memory");                             \
    }

#pragma unroll
    for (int k = 0; k < AGGQ; ++k) {
        if (dk[k] != cur_d) {
            FLUSH();
            acc = make_float4(0.f, 0.f, 0.f, 0.f);
            cur_d = dk[k];
        }
        int tt = pk[k] >> 17;
        float c0 = scomp[2 * tt], c1 = scomp[2 * tt + 1];
        float2 f0a = __half22float2(*(__half2*)&a[k].x);
        float2 f0b = __half22float2(*(__half2*)&a[k].y);
        float2 f1a = __half22float2(*(__half2*)&a[k].z);
        float2 f1b = __half22float2(*(__half2*)&a[k].w);
        acc.x = fmaf(c0, f0a.x, fmaf(c1, f1a.x, acc.x));
        acc.y = fmaf(c0, f0a.y, fmaf(c1, f1a.y, acc.y));
        acc.z = fmaf(c0, f0b.x, fmaf(c1, f1b.x, acc.z));
        acc.w = fmaf(c0, f0b.y, fmaf(c1, f1b.y, acc.w));
    }
    FLUSH();
#undef FLUSH
}

// ---------------------------------------------------------------------------
// FC readout
// ---------------------------------------------------------------------------
__global__ void __launch_bounds__(256) fc_kernel(
    const float4* __restrict__ a, const float4* __restrict__ w,
    const float* __restrict__ fc_b, float* __restrict__ out)
{
    int tid = blockIdx.x * 256 + threadIdx.x;
    float s = 0.f;
    for (int i = tid; i < NN * 16; i += 512 * 256) {
        float4 xa = a[i], xw = w[i];
        s += xa.x * xw.x + xa.y * xw.y + xa.z * xw.z + xa.w * xw.w;
    }
    __shared__ float red[256];
    red[threadIdx.x] = s;
    __syncthreads();
    for (int st = 128; st > 0; st >>= 1) {
        if (threadIdx.x < st) red[threadIdx.x] += red[threadIdx.x + st];
        __syncthreads();
    }
    if (threadIdx.x == 0) {
        atomicAdd(&g_facc, red[0]);
        __threadfence();
        int c = atomicAdd(&g_fcnt, 1);
        if (c == 511) {
            float tot = atomicAdd(&g_facc, 0.f);
            out[0] = 1.f / (1.f + expf(-(tot + fc_b[0])));
        }
    }
}

// ---------------------------------------------------------------------------
extern "C" void kernel_launch(void* const* d_in, const int* in_sizes, int n_in,
                              void* d_out, int out_size)
{
    const float* features = (const float*)d_in[0];
    const float* V        = (const float*)d_in[1];
    const float* comp     = (const float*)d_in[2];
    const float* loop_w   = (const float*)d_in[3];
    const float* bias     = (const float*)d_in[4];
    const float* fc_w     = (const float*)d_in[5];
    const float* fc_b     = (const float*)d_in[6];
    const int*   src      = (const int*)d_in[7];
    const int*   dst      = (const int*)d_in[8];
    const int*   et       = (const int*)d_in[9];
    float* out = (float*)d_out;

    void *p_projh, *p_h1, *p_h2, *p_deg, *p_cur, *p_tflag, *p_csr;
    cudaGetSymbolAddress(&p_projh, g_projh);
    cudaGetSymbolAddress(&p_h1, g_h1a);
    cudaGetSymbolAddress(&p_h2, g_h2a);
    cudaGetSymbolAddress(&p_deg, g_deg);
    cudaGetSymbolAddress(&p_cur, g_cursor);
    cudaGetSymbolAddress(&p_tflag, g_tflag);
    cudaGetSymbolAddress(&p_csr, g_csr);

    cudaFuncSetAttribute(gemm_tc,
                         cudaFuncAttributeMaxDynamicSharedMemorySize, GEMM_SMEM);

    const int e4_blocks   = (NE / 4 + 255) / 256;
    const int e1_blocks   = (NE + 255) / 256;
    const int gemm_blocks = (NN + 63) / 64;
    const int agg_blocks  = ((NE / AGGQ) * 16 + 255) / 256;

    cudaStream_t s2;
    cudaStreamCreateWithFlags(&s2, cudaStreamNonBlocking);
    cudaEvent_t eFork, eJoin, ePref;
    cudaEventCreateWithFlags(&eFork, cudaEventDisableTiming);
    cudaEventCreateWithFlags(&eJoin, cudaEventDisableTiming);
    cudaEventCreateWithFlags(&ePref, cudaEventDisableTiming);

    cudaEventRecord(eFork, 0);
    cudaStreamWaitEvent(s2, eFork, 0);

    // gemm0 starts immediately (weights staged in-kernel; no wprep).
    gemm_tc<<<gemm_blocks, 256, GEMM_SMEM>>>(features, V, loop_w, bias,
                                             (__half*)p_projh, (float*)p_h1,
                                             0);                           // 0
    hist_kernel<<<e4_blocks, 256, 0, s2>>>((const int4*)dst, (int*)p_deg); // 1
    scan_kernel<<<NTILES, 512, 0, s2>>>((int*)p_deg, (int*)p_cur,
                                        (int*)p_tflag);                    // 2
    scatter_kernel<<<e1_blocks, 256, 0, s2>>>(src, dst, et, (int*)p_cur,
                                              (int2*)p_csr, (int*)p_tflag);// 3
    cudaEventRecord(eJoin, s2);
    prefetch_kernel<<<256, 256, 0, s2>>>((const float4*)fc_w);             // 4
    cudaEventRecord(ePref, s2);

    cudaStreamWaitEvent(0, eJoin, 0);   // csr ready for agg0

    agg_kernel<<<agg_blocks, 256>>>((const uint4*)p_projh, (const int2*)p_csr,
                                    comp, (float4*)p_h1);                  // 5
    gemm_tc<<<gemm_blocks, 256, GEMM_SMEM>>>((const float*)p_h1, V + 8192,
                                             loop_w + 4096, bias + 64,
                                             (__half*)p_projh, (float*)p_h2,
                                             1);                           // 6
    agg_kernel<<<agg_blocks, 256>>>((const uint4*)p_projh, (const int2*)p_csr,
                                    comp + 16, (float4*)p_h2);             // 7

    cudaStreamWaitEvent(0, ePref, 0);
    fc_kernel<<<512, 256>>>((const float4*)p_h2, (const float4*)fc_w, fc_b,
                            out);                                          // 8

    cudaEventDestroy(eFork);
    cudaEventDestroy(eJoin);
    cudaEventDestroy(ePref);
    cudaStreamDestroy(s2);
}

// round 15
// speedup vs baseline: 1.0823x; 1.0823x over previous
#include <cuda_runtime.h>
#include <cuda_fp16.h>
#include <math.h>

#define NN 50000
#define NE 800000
#define NTILES 98      // ceil((NN+1)/512)
#define GSTRIDE 68     // A smem stride (conflict-free frag loads)
#define AGGQ 8         // edges per half-warp quota

// ---------------- scratch (static __device__, allocation-free) ----------------
__device__ uint4  g_projh[NN * 16];     // [N][16] x 16B: {b0 4h | b1 4h} per sub
__device__ float4 g_h1a[NN * 16];       // layer-1 hidden fp32
__device__ float4 g_h2a[NN * 16];       // layer-2 hidden fp32
__device__ int    g_deg[NN];            // self-clearing (scan zeroes after read)
__device__ int    g_cursor[NN];
__device__ int    g_tflag[128];         // cleared by scatter each run
__device__ int2   g_csr[NE];            // {src | etype<<17, dst}
__device__ uint2  g_wpack[2 * 24 * 8 * 32];   // frag-major tf32 weights
__device__ float  g_facc;
__device__ int    g_fcnt;
__device__ float  g_sink;

static __device__ __forceinline__ unsigned f2tf32(float f)
{
    unsigned u;
    asm("cvt.rna.tf32.f32 %0, %1;" : "=r"(u) : "f"(f));
    return u;
}

static __device__ __forceinline__ void pdl_wait()
{
    asm volatile("griddepcontrol.wait;" ::: "memory");
}

// ---------------- CSR build (side stream) ----------------
__global__ void __launch_bounds__(256) hist_kernel(const int4* __restrict__ dst4,
                                                   int* __restrict__ deg)
{
    int t = blockIdx.x * 256 + threadIdx.x;
    if (t >= NE / 4) return;
    int4 d = __ldg(dst4 + t);
    atomicAdd(&deg[d.x], 1);
    atomicAdd(&deg[d.y], 1);
    atomicAdd(&deg[d.z], 1);
    atomicAdd(&deg[d.w], 1);
}

// Warp-shuffle decoupled-lookback scan; self-clears deg for the next replay.
__global__ void __launch_bounds__(512) scan_kernel(
    int* __restrict__ deg, int* __restrict__ cursor, int* __restrict__ tflag)
{
    __shared__ int wsum[16];
    __shared__ int wpre[16];
    __shared__ int s_prefix;
    const int t = threadIdx.x;
    const int warp = t >> 5;
    const int lane = t & 31;
    const int tile = blockIdx.x;
    const int g = tile * 512 + t;

    int v = (g < NN) ? deg[g] : 0;
    int x = v;
#pragma unroll
    for (int d = 1; d < 32; d <<= 1) {
        int y = __shfl_up_sync(0xFFFFFFFFu, x, d);
        if (lane >= d) x += y;
    }
    if (lane == 31) wsum[warp] = x;
    if (t == 32) s_prefix = 0;
    __syncthreads();

    if (warp == 0 && lane < 16) {
        int s = wsum[lane];
        int p = s;
#pragma unroll
        for (int d = 1; d < 16; d <<= 1) {
            int y = __shfl_up_sync(0xFFFFu, p, d);
            if (lane >= d) p += y;
        }
        wpre[lane] = p - s;
        if (lane == 15) atomicExch(&tflag[tile], p + 1);
    }

    if (tile > 0 && warp == 1) {
        int sum = 0;
        for (int base = tile - 1; base >= 0; base -= 32) {
            int idx = base - lane;
            int val = 0;
            if (idx >= 0) {
                int f;
                do { f = atomicAdd(&tflag[idx], 0); } while (f == 0);
                val = f - 1;
            }
#pragma unroll
            for (int o = 16; o; o >>= 1) val += __shfl_xor_sync(0xFFFFFFFFu, val, o);
            sum += val;
        }
        if (lane == 0) s_prefix = sum;
    }
    __syncthreads();

    if (g < NN) {
        cursor[g] = s_prefix + wpre[warp] + x - v;
        deg[g] = 0;
    }
}

// 1 edge/thread; block 0 clears tflag (stream-ordered after scan).
__global__ void __launch_bounds__(256) scatter_kernel(
    const int* __restrict__ src, const int* __restrict__ dst,
    const int* __restrict__ et, int* __restrict__ cursor,
    int2* __restrict__ csr, int* __restrict__ tflag)
{
    if (blockIdx.x == 0 && threadIdx.x < 128) tflag[threadIdx.x] = 0;
    int e = blockIdx.x * 256 + threadIdx.x;
    if (e >= NE) return;
    int d = __ldg(dst + e);
    int pos = atomicAdd(&cursor[d], 1);
    csr[pos] = make_int2(__ldg(src + e) | (__ldg(et + e) << 17), d);
}

// L2 warmer for fc_w
__global__ void __launch_bounds__(256) prefetch_kernel(const float4* __restrict__ w)
{
    int tid = blockIdx.x * 256 + threadIdx.x;
    float s = 0.f;
    for (int i = tid; i < NN * 16; i += 256 * 256) {
        float4 v = __ldg(w + i);
        s += v.x + v.y + v.z + v.w;
    }
    if (s == 1.2345e37f) g_sink = s;
}

// ---------------------------------------------------------------------------
// Weight prep + FC accumulator reset
// ---------------------------------------------------------------------------
__global__ void __launch_bounds__(256) wprep_kernel(
    const float* __restrict__ V, const float* __restrict__ lw,
    uint2* __restrict__ wpack)
{
    int id = blockIdx.x * 256 + threadIdx.x;
    if (id == 0) { g_facc = 0.f; g_fcnt = 0; }
    if (id >= 2 * 24 * 8 * 32) return;
    int lay  = id / 6144;
    int r    = id - lay * 6144;
    int nt   = r >> 8;
    int s    = (r >> 5) & 7;
    int lane = r & 31;
    int o  = nt * 8 + (lane >> 2);
    int k0 = s * 8 + (lane & 3);
    float w0, w1;
    if (o < 128) {
        int b = o >> 6, c = o & 63;
        w0 = V[(((lay * 2 + b) * 64) + k0) * 64 + c];
        w1 = V[(((lay * 2 + b) * 64) + k0 + 4) * 64 + c];
    } else {
        w0 = lw[(lay * 64 + k0) * 64 + (o - 128)];
        w1 = lw[(lay * 64 + k0 + 4) * 64 + (o - 128)];
    }
    wpack[id] = make_uint2(f2tf32(w0), f2tf32(w1));
}

// ---------------------------------------------------------------------------
// Tensor-core node GEMM: [50000x64] @ [64x192] via mma.sync.m16n8k8.tf32.
// Smem-staged coalesced epilogue; 3 CTAs/SM.
// PDL: pdl_early=1 (gemm0, dep=wprep/wpack) waits AFTER independent A-stage;
//      pdl_early=0 (gemm1, dep=agg0/h1) waits BEFORE A-stage.
// ---------------------------------------------------------------------------
__global__ void __launch_bounds__(256, 3) gemm_tc(
    const float* __restrict__ x, const uint2* __restrict__ wpack,
    const float* __restrict__ bias, __half* __restrict__ projh,
    float* __restrict__ h, int relu_in, int pdl_early)
{
    __shared__ unsigned xs[64 * GSTRIDE];     // 17408 B; reused as epilogue stage
    const int tid = threadIdx.x;
    const int nbase = blockIdx.x * 64;

    if (!pdl_early) pdl_wait();     // gemm1: x = h1 written by agg0

    {
        int nl = tid >> 2;
        int c0 = (tid & 3) * 16;
        int n = nbase + nl;
        const float4* xr = (const float4*)(x + (size_t)n * 64 + c0);
#pragma unroll
        for (int u = 0; u < 4; ++u) {
            float4 v = (n < NN) ? __ldg(xr + u) : make_float4(0.f, 0.f, 0.f, 0.f);
            if (relu_in) {
                v.x = fmaxf(v.x, 0.f); v.y = fmaxf(v.y, 0.f);
                v.z = fmaxf(v.z, 0.f); v.w = fmaxf(v.w, 0.f);
            }
            unsigned* dstp = xs + nl * GSTRIDE + c0 + u * 4;
            dstp[0] = f2tf32(v.x); dstp[1] = f2tf32(v.y);
            dstp[2] = f2tf32(v.z); dstp[3] = f2tf32(v.w);
        }
    }

    if (pdl_early) pdl_wait();      // gemm0: wpack written by wprep
    __syncthreads();

    const int w    = tid >> 5;
    const int lane = tid & 31;
    const int m0   = (w & 3) << 4;
    const int ng   = w >> 2;
    const int g    = lane >> 2;
    const int t4   = lane & 3;

    float acc[12][4];
#pragma unroll
    for (int j = 0; j < 12; ++j)
#pragma unroll
        for (int c = 0; c < 4; ++c) acc[j][c] = 0.f;

    const uint2* wp = wpack + ((size_t)ng * 12 * 8 * 32) + lane;

#pragma unroll
    for (int s = 0; s < 8; ++s) {
        int k0 = s * 8;
        unsigned a0 = xs[(m0 + g) * GSTRIDE + k0 + t4];
        unsigned a1 = xs[(m0 + g + 8) * GSTRIDE + k0 + t4];
        unsigned a2 = xs[(m0 + g) * GSTRIDE + k0 + t4 + 4];
        unsigned a3 = xs[(m0 + g + 8) * GSTRIDE + k0 + t4 + 4];
        uint2 b[12];
#pragma unroll
        for (int j = 0; j < 12; ++j) b[j] = __ldg(wp + (j * 8 + s) * 32);
#pragma unroll
        for (int j = 0; j < 12; ++j)
            asm volatile(
                "mma.sync.aligned.m16n8k8.row.col.f32.tf32.tf32.f32 "
                "{%0,%1,%2,%3}, {%4,%5,%6,%7}, {%8,%9}, {%0,%1,%2,%3};"
                : "+f"(acc[j][0]), "+f"(acc[j][1]), "+f"(acc[j][2]), "+f"(acc[j][3])
                : "r"(a0), "r"(a1), "r"(a2), "r"(a3), "r"(b[j].x), "r"(b[j].y));
    }
    __syncthreads();    // all warps done reading xs; safe to reuse

    // ---- Phase 1: proj (fp16, interleaved layout) via smem, coalesced ----
    {
        __half* sp = (__half*)xs;             // [64][132] halves
#pragma unroll
        for (int j = 0; j < 12; ++j) {
            int o = ng * 96 + j * 8 + t4 * 2;
            if (o < 128) {
                int basis = o >> 6, c64 = o & 63;
                int off = ((c64 >> 2) << 3) + (basis << 2) + (c64 & 3);
#pragma unroll
                for (int rr = 0; rr < 2; ++rr) {
                    int nl = m0 + g + rr * 8;
                    *(__half2*)(sp + nl * 132 + off) =
                        __floats2half2_rn(acc[j][rr * 2], acc[j][rr * 2 + 1]);
                }
            }
        }
        __syncthreads();
        const unsigned* sp32 = (const unsigned*)xs;
        for (int idx = tid; idx < 1024; idx += 256) {
            int nl = idx >> 4, sub = idx & 15;
            int n = nbase + nl;
            if (n < NN) {
                int wi = nl * 66 + sub * 4;
                uint4 v = make_uint4(sp32[wi], sp32[wi + 1], sp32[wi + 2], sp32[wi + 3]);
                ((uint4*)projh)[(size_t)n * 16 + sub] = v;
            }
        }
        __syncthreads();
    }

    // ---- Phase 2: h (fp32 + bias) via smem, coalesced ----
    {
        float* hp = (float*)xs;               // [64][66] floats
        if (ng == 1) {
#pragma unroll
            for (int j = 4; j < 12; ++j) {
                int o = 96 + j * 8 + t4 * 2;  // >= 128
                int c = o - 128;
                float b0 = __ldg(bias + c), b1 = __ldg(bias + c + 1);
#pragma unroll
                for (int rr = 0; rr < 2; ++rr) {
                    int nl = m0 + g + rr * 8;
                    float2 f;
                    f.x = acc[j][rr * 2] + b0;
                    f.y = acc[j][rr * 2 + 1] + b1;
                    *(float2*)(hp + nl * 66 + c) = f;
                }
            }
        }
        __syncthreads();
        const float* hf = (const float*)xs;
        for (int idx = tid; idx < 1024; idx += 256) {
            int nl = idx >> 4, c4 = idx & 15;
            int n = nbase + nl;
            if (n < NN) {
                int wi = nl * 66 + c4 * 4;
                float4 v = make_float4(hf[wi], hf[wi + 1], hf[wi + 2], hf[wi + 3]);
                ((float4*)h)[(size_t)n * 16 + c4] = v;
            }
        }
    }
}

// ---------------------------------------------------------------------------
// Edge-balanced aggregation: half-warp per 8-edge CSR window.
// PDL: csr/scomp reads are independent of the upstream gemm (csr arrives via
// the regular event edge); wait before the proj gathers.
// ---------------------------------------------------------------------------
__global__ void __launch_bounds__(256) agg_kernel(
    const uint4* __restrict__ proj, const int2* __restrict__ csr,
    const float* __restrict__ comp_l, float4* __restrict__ h)
{
    __shared__ float scomp[16];
    if (threadIdx.x < 16) scomp[threadIdx.x] = comp_l[threadIdx.x];
    __syncthreads();

    int gid = blockIdx.x * 256 + threadIdx.x;
    int q = gid >> 4;
    if (q >= NE / AGGQ) { pdl_wait(); return; }
    int sub = gid & 15;
    int j0 = q * AGGQ;
    unsigned hmask = 0xFFFFu << (threadIdx.x & 16);

    int2 rec = (sub < AGGQ) ? __ldg(csr + j0 + sub) : make_int2(0, 0);

    int pk[AGGQ], dk[AGGQ];
#pragma unroll
    for (int k = 0; k < AGGQ; ++k) {
        pk[k] = __shfl_sync(hmask, rec.x, k, 16);
        dk[k] = __shfl_sync(hmask, rec.y, k, 16);
    }

    pdl_wait();    // proj (and h seed) written by the upstream gemm

    uint4 a[AGGQ];
#pragma unroll
    for (int k = 0; k < AGGQ; ++k)
        a[k] = __ldg(proj + (size_t)(pk[k] & 0x1FFFF) * 16 + sub);

    float4 acc = make_float4(0.f, 0.f, 0.f, 0.f);
    int cur_d = dk[0];

#define FLUSH()                                                             \
    {                                                                       \
        float4* hp = h + (size_t)cur_d * 16 + sub;                          \
        asm volatile("red.global.add.v4.f32 [%0], {%1,%2,%3,%4};"           \
                     :: "l"(hp), "f"(acc.x), "f"(acc.y), "f"(acc.z),        \
                        "f"(acc.w) : "memory");                             \
    }

#pragma unroll
    for (int k = 0; k < AGGQ; ++k) {
        if (dk[k] != cur_d) {
            FLUSH();
            acc = make_float4(0.f, 0.f, 0.f, 0.f);
            cur_d = dk[k];
        }
        int tt = pk[k] >> 17;
        float c0 = scomp[2 * tt], c1 = scomp[2 * tt + 1];
        float2 f0a = __half22float2(*(__half2*)&a[k].x);
        float2 f0b = __half22float2(*(__half2*)&a[k].y);
        float2 f1a = __half22float2(*(__half2*)&a[k].z);
        float2 f1b = __half22float2(*(__half2*)&a[k].w);
        acc.x = fmaf(c0, f0a.x, fmaf(c1, f1a.x, acc.x));
        acc.y = fmaf(c0, f0a.y, fmaf(c1, f1a.y, acc.y));
        acc.z = fmaf(c0, f0b.x, fmaf(c1, f1b.x, acc.z));
        acc.w = fmaf(c0, f0b.y, fmaf(c1, f1b.y, acc.w));
    }
    FLUSH();
#undef FLUSH
}

// ---------------------------------------------------------------------------
// FC readout (PDL: wait at top; h2 is the dependency)
// ---------------------------------------------------------------------------
__global__ void __launch_bounds__(256) fc_kernel(
    const float4* __restrict__ a, const float4* __restrict__ w,
    const float* __restrict__ fc_b, float* __restrict__ out)
{
    pdl_wait();
    int tid = blockIdx.x * 256 + threadIdx.x;
    float s = 0.f;
    for (int i = tid; i < NN * 16; i += 512 * 256) {
        float4 xa = a[i], xw = w[i];
        s += xa.x * xw.x + xa.y * xw.y + xa.z * xw.z + xa.w * xw.w;
    }
    __shared__ float red[256];
    red[threadIdx.x] = s;
    __syncthreads();
    for (int st = 128; st > 0; st >>= 1) {
        if (threadIdx.x < st) red[threadIdx.x] += red[threadIdx.x + st];
        __syncthreads();
    }
    if (threadIdx.x == 0) {
        atomicAdd(&g_facc, red[0]);
        __threadfence();
        int c = atomicAdd(&g_fcnt, 1);
        if (c == 511) {
            float tot = atomicAdd(&g_facc, 0.f);
            out[0] = 1.f / (1.f + expf(-(tot + fc_b[0])));
        }
    }
}

// ---------------------------------------------------------------------------
static void launch_pdl(const void* func, dim3 grid, dim3 block, void** args,
                       cudaStream_t s)
{
    cudaLaunchConfig_t cfg = {};
    cfg.gridDim = grid;
    cfg.blockDim = block;
    cfg.dynamicSmemBytes = 0;
    cfg.stream = s;
    cudaLaunchAttribute attr[1];
    attr[0].id = cudaLaunchAttributeProgrammaticStreamSerialization;
    attr[0].val.programmaticStreamSerializationAllowed = 1;
    cfg.attrs = attr;
    cfg.numAttrs = 1;
    cudaLaunchKernelExC(&cfg, func, args);
}

extern "C" void kernel_launch(void* const* d_in, const int* in_sizes, int n_in,
                              void* d_out, int out_size)
{
    const float* features = (const float*)d_in[0];
    const float* V        = (const float*)d_in[1];
    const float* comp     = (const float*)d_in[2];
    const float* loop_w   = (const float*)d_in[3];
    const float* bias     = (const float*)d_in[4];
    const float* fc_w     = (const float*)d_in[5];
    const float* fc_b     = (const float*)d_in[6];
    const int*   src      = (const int*)d_in[7];
    const int*   dst      = (const int*)d_in[8];
    const int*   et       = (const int*)d_in[9];
    float* out = (float*)d_out;

    void *p_projh, *p_h1, *p_h2, *p_deg, *p_cur, *p_tflag, *p_csr, *p_wp;
    cudaGetSymbolAddress(&p_projh, g_projh);
    cudaGetSymbolAddress(&p_h1, g_h1a);
    cudaGetSymbolAddress(&p_h2, g_h2a);
    cudaGetSymbolAddress(&p_deg, g_deg);
    cudaGetSymbolAddress(&p_cur, g_cursor);
    cudaGetSymbolAddress(&p_tflag, g_tflag);
    cudaGetSymbolAddress(&p_csr, g_csr);
    cudaGetSymbolAddress(&p_wp, g_wpack);

    const int e4_blocks   = (NE / 4 + 255) / 256;
    const int e1_blocks   = (NE + 255) / 256;
    const int gemm_blocks = (NN + 63) / 64;
    const int agg_blocks  = ((NE / AGGQ) * 16 + 255) / 256;

    cudaStream_t s2;
    cudaStreamCreateWithFlags(&s2, cudaStreamNonBlocking);
    cudaEvent_t eFork, eJoin, ePref;
    cudaEventCreateWithFlags(&eFork, cudaEventDisableTiming);
    cudaEventCreateWithFlags(&eJoin, cudaEventDisableTiming);
    cudaEventCreateWithFlags(&ePref, cudaEventDisableTiming);

    cudaEventRecord(eFork, 0);
    cudaStreamWaitEvent(s2, eFork, 0);

    // --- launch args ---
    const uint2* wp0 = (const uint2*)p_wp;
    const uint2* wp1 = (const uint2*)p_wp + 6144;
    const float* bias1 = bias + 64;
    __half* projh = (__half*)p_projh;
    float* h1 = (float*)p_h1;
    float* h2 = (float*)p_h2;
    const float* x1 = (const float*)p_h1;
    const uint4* proj4 = (const uint4*)p_projh;
    const int2* csr = (const int2*)p_csr;
    const float* comp1 = comp + 16;
    const float4* fcw4 = (const float4*)fc_w;
    const float4* h2c = (const float4*)p_h2;
    int zero = 0, one = 1;
    const float* Vl1 = V + 8192;
    const float* lwl1 = loop_w + 4096;

    wprep_kernel<<<48, 256>>>(V, loop_w, (uint2*)p_wp);                    // 0
    hist_kernel<<<e4_blocks, 256, 0, s2>>>((const int4*)dst, (int*)p_deg); // 1
    scan_kernel<<<NTILES, 512, 0, s2>>>((int*)p_deg, (int*)p_cur,
                                        (int*)p_tflag);                    // 2
    {   // gemm0: PDL secondary of wprep (early wait)
        void* args[] = {(void*)&features, (void*)&wp0, (void*)&bias,
                        (void*)&projh, (void*)&h1, (void*)&zero, (void*)&one};
        launch_pdl((const void*)gemm_tc, dim3(gemm_blocks), dim3(256), args, 0);
    }                                                                      // 3
    scatter_kernel<<<e1_blocks, 256, 0, s2>>>(src, dst, et, (int*)p_cur,
                                              (int2*)p_csr, (int*)p_tflag);// 4
    cudaEventRecord(eJoin, s2);
    prefetch_kernel<<<256, 256, 0, s2>>>((const float4*)fc_w);             // 5
    cudaEventRecord(ePref, s2);

    cudaStreamWaitEvent(0, eJoin, 0);   // csr/cursor ready for agg0

    {   // agg0: PDL secondary of gemm0
        void* args[] = {(void*)&proj4, (void*)&csr, (void*)&comp, (void*)&h1};
        launch_pdl((const void*)agg_kernel, dim3(agg_blocks), dim3(256), args, 0);
    }                                                                      // 6
    {   // gemm1: PDL secondary of agg0 (wait before h1 read)
        void* args[] = {(void*)&x1, (void*)&wp1, (void*)&bias1,
                        (void*)&projh, (void*)&h2, (void*)&one, (void*)&zero};
        launch_pdl((const void*)gemm_tc, dim3(gemm_blocks), dim3(256), args, 0);
    }                                                                      // 7
    {   // agg1: PDL secondary of gemm1
        void* args[] = {(void*)&proj4, (void*)&csr, (void*)&comp1, (void*)&h2};
        launch_pdl((const void*)agg_kernel, dim3(agg_blocks), dim3(256), args, 0);
    }                                                                      // 8

    cudaStreamWaitEvent(0, ePref, 0);
    {   // fc: PDL secondary of agg1
        void* args[] = {(void*)&h2c, (void*)&fcw4, (void*)&fc_b, (void*)&out};
        launch_pdl((const void*)fc_kernel, dim3(512), dim3(256), args, 0);
    }                                                                      // 9

    cudaEventDestroy(eFork);
    cudaEventDestroy(eJoin);
    cudaEventDestroy(ePref);
    cudaStreamDestroy(s2);
}

// round 16
// speedup vs baseline: 1.0830x; 1.0006x over previous
#include <cuda_runtime.h>
#include <cuda_fp16.h>
#include <math.h>

#define NN 50000
#define NE 800000
#define NTILES 98      // ceil((50000+1)/512)
#define GSTRIDE 68     // A smem stride (conflict-free frag loads)
#define AGGQ 8         // edges per half-warp quota

// ---------------- scratch (static __device__, allocation-free) ----------------
__device__ uint4  g_projh[NN * 16];     // [N][16] x 16B: {b0 4h | b1 4h} per sub
__device__ float4 g_h1a[NN * 16];       // layer-1 hidden fp32
__device__ float4 g_h2a[NN * 16];       // layer-2 hidden fp32
__device__ int    g_deg[NN];            // self-clearing (scan zeroes after read)
__device__ int    g_cursor[NN];
__device__ int    g_tflag[128];         // cleared by scatter each run
__device__ int2   g_csr[NE];            // {src | etype<<17, dst}
__device__ uint2  g_wpack[2 * 24 * 8 * 32];   // frag-major tf32 weights
__device__ float  g_facc;
__device__ int    g_fcnt;
__device__ int    g_sink;

static __device__ __forceinline__ unsigned f2tf32(float f)
{
    unsigned u;
    asm("cvt.rna.tf32.f32 %0, %1;" : "=r"(u) : "f"(f));
    return u;
}

static __device__ __forceinline__ void pdl_wait()
{
    asm volatile("griddepcontrol.wait;" ::: "memory");
}

// ---------------- CSR build (side stream) ----------------
// hist also streams src/et through L2 so scatter's gathers L2-hit.
__global__ void __launch_bounds__(256) hist_kernel(
    const int4* __restrict__ dst4, const int4* __restrict__ src4,
    const int4* __restrict__ et4, int* __restrict__ deg)
{
    int t = blockIdx.x * 256 + threadIdx.x;
    if (t >= NE / 4) return;
    int4 d = __ldg(dst4 + t);
    int4 s = __ldg(src4 + t);            // L2 warm for scatter
    int4 e = __ldg(et4 + t);             // L2 warm for scatter
    atomicAdd(&deg[d.x], 1);
    atomicAdd(&deg[d.y], 1);
    atomicAdd(&deg[d.z], 1);
    atomicAdd(&deg[d.w], 1);
    int chk = s.x ^ s.y ^ s.z ^ s.w ^ e.x ^ e.y ^ e.z ^ e.w;
    if (chk == (int)0xDEADBEEF && t == 0x7FFFFFF0) g_sink = chk;  // keep loads
}

// Warp-shuffle decoupled-lookback scan; self-clears deg for the next replay.
__global__ void __launch_bounds__(512) scan_kernel(
    int* __restrict__ deg, int* __restrict__ cursor, int* __restrict__ tflag)
{
    __shared__ int wsum[16];
    __shared__ int wpre[16];
    __shared__ int s_prefix;
    const int t = threadIdx.x;
    const int warp = t >> 5;
    const int lane = t & 31;
    const int tile = blockIdx.x;
    const int g = tile * 512 + t;

    int v = (g < NN) ? deg[g] : 0;
    int x = v;
#pragma unroll
    for (int d = 1; d < 32; d <<= 1) {
        int y = __shfl_up_sync(0xFFFFFFFFu, x, d);
        if (lane >= d) x += y;
    }
    if (lane == 31) wsum[warp] = x;
    if (t == 32) s_prefix = 0;
    __syncthreads();

    if (warp == 0 && lane < 16) {
        int s = wsum[lane];
        int p = s;
#pragma unroll
        for (int d = 1; d < 16; d <<= 1) {
            int y = __shfl_up_sync(0xFFFFu, p, d);
            if (lane >= d) p += y;
        }
        wpre[lane] = p - s;
        if (lane == 15) atomicExch(&tflag[tile], p + 1);
    }

    if (tile > 0 && warp == 1) {
        int sum = 0;
        for (int base = tile - 1; base >= 0; base -= 32) {
            int idx = base - lane;
            int val = 0;
            if (idx >= 0) {
                int f;
                do { f = atomicAdd(&tflag[idx], 0); } while (f == 0);
                val = f - 1;
            }
#pragma unroll
            for (int o = 16; o; o >>= 1) val += __shfl_xor_sync(0xFFFFFFFFu, val, o);
            sum += val;
        }
        if (lane == 0) s_prefix = sum;
    }
    __syncthreads();

    if (g < NN) {
        cursor[g] = s_prefix + wpre[warp] + x - v;
        deg[g] = 0;
    }
}

// 1 edge/thread; block 0 clears tflag (stream-ordered after scan).
__global__ void __launch_bounds__(256) scatter_kernel(
    const int* __restrict__ src, const int* __restrict__ dst,
    const int* __restrict__ et, int* __restrict__ cursor,
    int2* __restrict__ csr, int* __restrict__ tflag)
{
    if (blockIdx.x == 0 && threadIdx.x < 128) tflag[threadIdx.x] = 0;
    int e = blockIdx.x * 256 + threadIdx.x;
    if (e >= NE) return;
    int d = __ldg(dst + e);
    int pos = atomicAdd(&cursor[d], 1);
    csr[pos] = make_int2(__ldg(src + e) | (__ldg(et + e) << 17), d);
}

// L2 warmer for fc_w
__global__ void __launch_bounds__(256) prefetch_kernel(const float4* __restrict__ w)
{
    int tid = blockIdx.x * 256 + threadIdx.x;
    float s = 0.f;
    for (int i = tid; i < NN * 16; i += 256 * 256) {
        float4 v = __ldg(w + i);
        s += v.x + v.y + v.z + v.w;
    }
    if (s == 1.2345e37f) g_sink = 1;
}

// ---------------------------------------------------------------------------
// Weight prep + FC accumulator reset
// ---------------------------------------------------------------------------
__global__ void __launch_bounds__(256) wprep_kernel(
    const float* __restrict__ V, const float* __restrict__ lw,
    uint2* __restrict__ wpack)
{
    int id = blockIdx.x * 256 + threadIdx.x;
    if (id == 0) { g_facc = 0.f; g_fcnt = 0; }
    if (id >= 2 * 24 * 8 * 32) return;
    int lay  = id / 6144;
    int r    = id - lay * 6144;
    int nt   = r >> 8;
    int s    = (r >> 5) & 7;
    int lane = r & 31;
    int o  = nt * 8 + (lane >> 2);
    int k0 = s * 8 + (lane & 3);
    float w0, w1;
    if (o < 128) {
        int b = o >> 6, c = o & 63;
        w0 = V[(((lay * 2 + b) * 64) + k0) * 64 + c];
        w1 = V[(((lay * 2 + b) * 64) + k0 + 4) * 64 + c];
    } else {
        w0 = lw[(lay * 64 + k0) * 64 + (o - 128)];
        w1 = lw[(lay * 64 + k0 + 4) * 64 + (o - 128)];
    }
    wpack[id] = make_uint2(f2tf32(w0), f2tf32(w1));
}

// ---------------------------------------------------------------------------
// Tensor-core node GEMM: [50000x64] @ [64x192] via mma.sync.m16n8k8.tf32.
// Smem-staged coalesced epilogue; 3 CTAs/SM.
// PDL: pdl_early=1 (gemm0, dep=wprep/wpack) waits AFTER independent A-stage;
//      pdl_early=0 (gemm1, dep=agg0/h1) waits BEFORE A-stage.
// ---------------------------------------------------------------------------
__global__ void __launch_bounds__(256, 3) gemm_tc(
    const float* __restrict__ x, const uint2* __restrict__ wpack,
    const float* __restrict__ bias, __half* __restrict__ projh,
    float* __restrict__ h, int relu_in, int pdl_early)
{
    __shared__ unsigned xs[64 * GSTRIDE];     // 17408 B; reused as epilogue stage
    const int tid = threadIdx.x;
    const int nbase = blockIdx.x * 64;

    if (!pdl_early) pdl_wait();     // gemm1: x = h1 written by agg0

    {
        int nl = tid >> 2;
        int c0 = (tid & 3) * 16;
        int n = nbase + nl;
        const float4* xr = (const float4*)(x + (size_t)n * 64 + c0);
#pragma unroll
        for (int u = 0; u < 4; ++u) {
            float4 v = (n < NN) ? __ldg(xr + u) : make_float4(0.f, 0.f, 0.f, 0.f);
            if (relu_in) {
                v.x = fmaxf(v.x, 0.f); v.y = fmaxf(v.y, 0.f);
                v.z = fmaxf(v.z, 0.f); v.w = fmaxf(v.w, 0.f);
            }
            unsigned* dstp = xs + nl * GSTRIDE + c0 + u * 4;
            dstp[0] = f2tf32(v.x); dstp[1] = f2tf32(v.y);
            dstp[2] = f2tf32(v.z); dstp[3] = f2tf32(v.w);
        }
    }

    if (pdl_early) pdl_wait();      // gemm0: wpack written by wprep
    __syncthreads();

    const int w    = tid >> 5;
    const int lane = tid & 31;
    const int m0   = (w & 3) << 4;
    const int ng   = w >> 2;
    const int g    = lane >> 2;
    const int t4   = lane & 3;

    float acc[12][4];
#pragma unroll
    for (int j = 0; j < 12; ++j)
#pragma unroll
        for (int c = 0; c < 4; ++c) acc[j][c] = 0.f;

    const uint2* wp = wpack + ((size_t)ng * 12 * 8 * 32) + lane;

#pragma unroll
    for (int s = 0; s < 8; ++s) {
        int k0 = s * 8;
        unsigned a0 = xs[(m0 + g) * GSTRIDE + k0 + t4];
        unsigned a1 = xs[(m0 + g + 8) * GSTRIDE + k0 + t4];
        unsigned a2 = xs[(m0 + g) * GSTRIDE + k0 + t4 + 4];
        unsigned a3 = xs[(m0 + g + 8) * GSTRIDE + k0 + t4 + 4];
        uint2 b[12];
#pragma unroll
        for (int j = 0; j < 12; ++j) b[j] = __ldg(wp + (j * 8 + s) * 32);
#pragma unroll
        for (int j = 0; j < 12; ++j)
            asm volatile(
                "mma.sync.aligned.m16n8k8.row.col.f32.tf32.tf32.f32 "
                "{%0,%1,%2,%3}, {%4,%5,%6,%7}, {%8,%9}, {%0,%1,%2,%3};"
                : "+f"(acc[j][0]), "+f"(acc[j][1]), "+f"(acc[j][2]), "+f"(acc[j][3])
                : "r"(a0), "r"(a1), "r"(a2), "r"(a3), "r"(b[j].x), "r"(b[j].y));
    }
    __syncthreads();    // all warps done reading xs; safe to reuse

    // ---- Phase 1: proj (fp16, interleaved layout) via smem, coalesced ----
    {
        __half* sp = (__half*)xs;             // [64][132] halves
#pragma unroll
        for (int j = 0; j < 12; ++j) {
            int o = ng * 96 + j * 8 + t4 * 2;
            if (o < 128) {
                int basis = o >> 6, c64 = o & 63;
                int off = ((c64 >> 2) << 3) + (basis << 2) + (c64 & 3);
#pragma unroll
                for (int rr = 0; rr < 2; ++rr) {
                    int nl = m0 + g + rr * 8;
                    *(__half2*)(sp + nl * 132 + off) =
                        __floats2half2_rn(acc[j][rr * 2], acc[j][rr * 2 + 1]);
                }
            }
        }
        __syncthreads();
        const unsigned* sp32 = (const unsigned*)xs;
        for (int idx = tid; idx < 1024; idx += 256) {
            int nl = idx >> 4, sub = idx & 15;
            int n = nbase + nl;
            if (n < NN) {
                int wi = nl * 66 + sub * 4;
                uint4 v = make_uint4(sp32[wi], sp32[wi + 1], sp32[wi + 2], sp32[wi + 3]);
                ((uint4*)projh)[(size_t)n * 16 + sub] = v;
            }
        }
        __syncthreads();
    }

    // ---- Phase 2: h (fp32 + bias) via smem, coalesced ----
    {
        float* hp = (float*)xs;               // [64][66] floats
        if (ng == 1) {
#pragma unroll
            for (int j = 4; j < 12; ++j) {
                int o = 96 + j * 8 + t4 * 2;  // >= 128
                int c = o - 128;
                float b0 = __ldg(bias + c), b1 = __ldg(bias + c + 1);
#pragma unroll
                for (int rr = 0; rr < 2; ++rr) {
                    int nl = m0 + g + rr * 8;
                    float2 f;
                    f.x = acc[j][rr * 2] + b0;
                    f.y = acc[j][rr * 2 + 1] + b1;
                    *(float2*)(hp + nl * 66 + c) = f;
                }
            }
        }
        __syncthreads();
        const float* hf = (const float*)xs;
        for (int idx = tid; idx < 1024; idx += 256) {
            int nl = idx >> 4, c4 = idx & 15;
            int n = nbase + nl;
            if (n < NN) {
                int wi = nl * 66 + c4 * 4;
                float4 v = make_float4(hf[wi], hf[wi + 1], hf[wi + 2], hf[wi + 3]);
                ((float4*)h)[(size_t)n * 16 + c4] = v;
            }
        }
    }
}

// ---------------------------------------------------------------------------
// Edge-balanced aggregation: half-warp per 8-edge CSR window (grid exact).
// PDL: csr reads + shuffles before the wait; proj gathers after.
// ---------------------------------------------------------------------------
__global__ void __launch_bounds__(256) agg_kernel(
    const uint4* __restrict__ proj, const int2* __restrict__ csr,
    const float* __restrict__ comp_l, float4* __restrict__ h)
{
    __shared__ float scomp[16];
    if (threadIdx.x < 16) scomp[threadIdx.x] = comp_l[threadIdx.x];
    __syncthreads();

    int gid = blockIdx.x * 256 + threadIdx.x;
    int q = gid >> 4;
    int sub = gid & 15;
    int j0 = q * AGGQ;
    unsigned hmask = 0xFFFFu << (threadIdx.x & 16);

    int2 rec = (sub < AGGQ) ? __ldg(csr + j0 + sub) : make_int2(0, 0);

    int pk[AGGQ], dk[AGGQ];
#pragma unroll
    for (int k = 0; k < AGGQ; ++k) {
        pk[k] = __shfl_sync(hmask, rec.x, k, 16);
        dk[k] = __shfl_sync(hmask, rec.y, k, 16);
    }

    pdl_wait();    // proj (and h seed) written by the upstream gemm

    uint4 a[AGGQ];
#pragma unroll
    for (int k = 0; k < AGGQ; ++k)
        a[k] = __ldg(proj + (size_t)(pk[k] & 0x1FFFF) * 16 + sub);

    float4 acc = make_float4(0.f, 0.f, 0.f, 0.f);
    int cur_d = dk[0];

#define FLUSH()                                                             \
    {                                                                       \
        float4* hp = h + (size_t)cur_d * 16 + sub;                          \
        asm volatile("red.global.add.v4.f32 [%0], {%1,%2,%3,%4};"           \
                     :: "l"(hp), "f"(acc.x), "f"(acc.y), "f"(acc.z),        \
                        "f"(acc.w) : "memory");                             \
    }

#pragma unroll
    for (int k = 0; k < AGGQ; ++k) {
        if (dk[k] != cur_d) {
            FLUSH();
            acc = make_float4(0.f, 0.f, 0.f, 0.f);
            cur_d = dk[k];
        }
        int tt = pk[k] >> 17;
        float c0 = scomp[2 * tt], c1 = scomp[2 * tt + 1];
        float2 f0a = __half22float2(*(__half2*)&a[k].x);
        float2 f0b = __half22float2(*(__half2*)&a[k].y);
        float2 f1a = __half22float2(*(__half2*)&a[k].z);
        float2 f1b = __half22float2(*(__half2*)&a[k].w);
        acc.x = fmaf(c0, f0a.x, fmaf(c1, f1a.x, acc.x));
        acc.y = fmaf(c0, f0a.y, fmaf(c1, f1a.y, acc.y));
        acc.z = fmaf(c0, f0b.x, fmaf(c1, f1b.x, acc.z));
        acc.w = fmaf(c0, f0b.y, fmaf(c1, f1b.y, acc.w));
    }
    FLUSH();
#undef FLUSH
}

// ---------------------------------------------------------------------------
// FC readout (PDL: wait at top; h2 is the dependency)
// ---------------------------------------------------------------------------
__global__ void __launch_bounds__(256) fc_kernel(
    const float4* __restrict__ a, const float4* __restrict__ w,
    const float* __restrict__ fc_b, float* __restrict__ out)
{
    pdl_wait();
    int tid = blockIdx.x * 256 + threadIdx.x;
    float s = 0.f;
    for (int i = tid; i < NN * 16; i += 512 * 256) {
        float4 xa = a[i], xw = w[i];
        s += xa.x * xw.x + xa.y * xw.y + xa.z * xw.z + xa.w * xw.w;
    }
    __shared__ float red[256];
    red[threadIdx.x] = s;
    __syncthreads();
    for (int st = 128; st > 0; st >>= 1) {
        if (threadIdx.x < st) red[threadIdx.x] += red[threadIdx.x + st];
        __syncthreads();
    }
    if (threadIdx.x == 0) {
        atomicAdd(&g_facc, red[0]);
        __threadfence();
        int c = atomicAdd(&g_fcnt, 1);
        if (c == 511) {
            float tot = atomicAdd(&g_facc, 0.f);
            out[0] = 1.f / (1.f + expf(-(tot + fc_b[0])));
        }
    }
}

// ---------------------------------------------------------------------------
static void launch_pdl(const void* func, dim3 grid, dim3 block, void** args,
                       cudaStream_t s)
{
    cudaLaunchConfig_t cfg = {};
    cfg.gridDim = grid;
    cfg.blockDim = block;
    cfg.dynamicSmemBytes = 0;
    cfg.stream = s;
    cudaLaunchAttribute attr[1];
    attr[0].id = cudaLaunchAttributeProgrammaticStreamSerialization;
    attr[0].val.programmaticStreamSerializationAllowed = 1;
    cfg.attrs = attr;
    cfg.numAttrs = 1;
    cudaLaunchKernelExC(&cfg, func, args);
}

extern "C" void kernel_launch(void* const* d_in, const int* in_sizes, int n_in,
                              void* d_out, int out_size)
{
    const float* features = (const float*)d_in[0];
    const float* V        = (const float*)d_in[1];
    const float* comp     = (const float*)d_in[2];
    const float* loop_w   = (const float*)d_in[3];
    const float* bias     = (const float*)d_in[4];
    const float* fc_w     = (const float*)d_in[5];
    const float* fc_b     = (const float*)d_in[6];
    const int*   src      = (const int*)d_in[7];
    const int*   dst      = (const int*)d_in[8];
    const int*   et       = (const int*)d_in[9];
    float* out = (float*)d_out;

    void *p_projh, *p_h1, *p_h2, *p_deg, *p_cur, *p_tflag, *p_csr, *p_wp;
    cudaGetSymbolAddress(&p_projh, g_projh);
    cudaGetSymbolAddress(&p_h1, g_h1a);
    cudaGetSymbolAddress(&p_h2, g_h2a);
    cudaGetSymbolAddress(&p_deg, g_deg);
    cudaGetSymbolAddress(&p_cur, g_cursor);
    cudaGetSymbolAddress(&p_tflag, g_tflag);
    cudaGetSymbolAddress(&p_csr, g_csr);
    cudaGetSymbolAddress(&p_wp, g_wpack);

    const int e4_blocks   = (NE / 4 + 255) / 256;
    const int e1_blocks   = (NE + 255) / 256;
    const int gemm_blocks = (NN + 63) / 64;
    const int agg_blocks  = ((NE / AGGQ) * 16 + 255) / 256;

    cudaStream_t s2;
    cudaStreamCreateWithFlags(&s2, cudaStreamNonBlocking);
    cudaEvent_t eFork, eJoin, ePref;
    cudaEventCreateWithFlags(&eFork, cudaEventDisableTiming);
    cudaEventCreateWithFlags(&eJoin, cudaEventDisableTiming);
    cudaEventCreateWithFlags(&ePref, cudaEventDisableTiming);

    cudaEventRecord(eFork, 0);
    cudaStreamWaitEvent(s2, eFork, 0);

    // --- launch args ---
    const uint2* wp0 = (const uint2*)p_wp;
    const uint2* wp1 = (const uint2*)p_wp + 6144;
    const float* bias1 = bias + 64;
    __half* projh = (__half*)p_projh;
    float* h1 = (float*)p_h1;
    float* h2 = (float*)p_h2;
    const float* x1 = (const float*)p_h1;
    const uint4* proj4 = (const uint4*)p_projh;
    const int2* csr = (const int2*)p_csr;
    const float* comp1 = comp + 16;
    const float4* fcw4 = (const float4*)fc_w;
    const float4* h2c = (const float4*)p_h2;
    int zero = 0, one = 1;

    wprep_kernel<<<48, 256>>>(V, loop_w, (uint2*)p_wp);                    // 0
    hist_kernel<<<e4_blocks, 256, 0, s2>>>((const int4*)dst, (const int4*)src,
                                           (const int4*)et, (int*)p_deg);  // 1
    scan_kernel<<<NTILES, 512, 0, s2>>>((int*)p_deg, (int*)p_cur,
                                        (int*)p_tflag);                    // 2
    {   // gemm0: PDL secondary of wprep (early wait)
        void* args[] = {(void*)&features, (void*)&wp0, (void*)&bias,
                        (void*)&projh, (void*)&h1, (void*)&zero, (void*)&one};
        launch_pdl((const void*)gemm_tc, dim3(gemm_blocks), dim3(256), args, 0);
    }                                                                      // 3
    scatter_kernel<<<e1_blocks, 256, 0, s2>>>(src, dst, et, (int*)p_cur,
                                              (int2*)p_csr, (int*)p_tflag);// 4
    cudaEventRecord(eJoin, s2);
    prefetch_kernel<<<256, 256, 0, s2>>>((const float4*)fc_w);             // 5
    cudaEventRecord(ePref, s2);

    cudaStreamWaitEvent(0, eJoin, 0);   // csr/cursor ready for agg0

    {   // agg0: PDL secondary of gemm0
        void* args[] = {(void*)&proj4, (void*)&csr, (void*)&comp, (void*)&h1};
        launch_pdl((const void*)agg_kernel, dim3(agg_blocks), dim3(256), args, 0);
    }                                                                      // 6
    {   // gemm1: PDL secondary of agg0 (wait before h1 read)
        void* args[] = {(void*)&x1, (void*)&wp1, (void*)&bias1,
                        (void*)&projh, (void*)&h2, (void*)&one, (void*)&zero};
        launch_pdl((const void*)gemm_tc, dim3(gemm_blocks), dim3(256), args, 0);
    }                                                                      // 7
    {   // agg1: PDL secondary of gemm1
        void* args[] = {(void*)&proj4, (void*)&csr, (void*)&comp1, (void*)&h2};
        launch_pdl((const void*)agg_kernel, dim3(agg_blocks), dim3(256), args, 0);
    }                                                                      // 8

    cudaStreamWaitEvent(0, ePref, 0);
    {   // fc: PDL secondary of agg1
        void* args[] = {(void*)&h2c, (void*)&fcw4, (void*)&fc_b, (void*)&out};
        launch_pdl((const void*)fc_kernel, dim3(512), dim3(256), args, 0);
    }                                                                      // 9

    cudaEventDestroy(eFork);
    cudaEventDestroy(eJoin);
    cudaEventDestroy(ePref);
    cudaStreamDestroy(s2);
}